// round 16
// baseline (speedup 1.0000x reference)
#include <cuda_runtime.h>
#include <cuda_bf16.h>
#include <math.h>
#include <stdint.h>

#define BB 64
#define NN 4096
#define DD 128
#define SS 8
#define HH 256
#define N_ITERS 3
#define LN_EPS 1e-5f
#define QK_SCALE 0.08838834764831845f
#define CHUNK 64
#define NCHUNK (NN / CHUNK)
#define PF 132   // K chunk smem pitch in floats

// ---------------- device scratch ----------------
__device__ float g_K[BB * NN * DD];
__device__ float g_V[BB * NN * DD];
__device__ float g_slots[BB * SS * DD];
__device__ float g_q[BB * SS * DD];
__device__ float g_updp[NCHUNK * BB * SS * DD];
__device__ float g_normp[NCHUNK * BB * SS];
__device__ float g_wqt[DD * DD];
__device__ float g_wiht[DD * 3 * DD];
__device__ float g_whht[DD * 3 * DD];
__device__ float g_w1t[DD * HH];
__device__ float g_w2t[HH * DD];

__device__ __forceinline__ uint32_t smem_u32(const void* p) {
    uint32_t a;
    asm("{ .reg .u64 t; cvta.to.shared.u64 t, %1; cvt.u32.u64 %0, t; }"
        : "=r"(a) : "l"(p));
    return a;
}
__device__ __forceinline__ void ldsm_x4(uint32_t* r, uint32_t addr) {
    asm volatile("ldmatrix.sync.aligned.m8n8.x4.shared.b16 {%0,%1,%2,%3}, [%4];"
                 : "=r"(r[0]), "=r"(r[1]), "=r"(r[2]), "=r"(r[3]) : "r"(addr));
}
__device__ __forceinline__ void ldsm_x2(uint32_t* r, uint32_t addr) {
    asm volatile("ldmatrix.sync.aligned.m8n8.x2.shared.b16 {%0,%1}, [%2];"
                 : "=r"(r[0]), "=r"(r[1]) : "r"(addr));
}
__device__ __forceinline__ void mma_bf16(float* c, const uint32_t* a, const uint32_t* b) {
    asm volatile(
        "mma.sync.aligned.m16n8k16.row.col.f32.bf16.bf16.f32 "
        "{%0,%1,%2,%3}, {%4,%5,%6,%7}, {%8,%9}, {%0,%1,%2,%3};"
        : "+f"(c[0]), "+f"(c[1]), "+f"(c[2]), "+f"(c[3])
        : "r"(a[0]), "r"(a[1]), "r"(a[2]), "r"(a[3]), "r"(b[0]), "r"(b[1]));
}

// smem layout for sa_kv (bytes); pitch 136 bf16 (272B) de-conflicts ldmatrix
#define PA 136
#define S_BIAS 0
#define S_BH 1024
#define S_BL (S_BH + 256 * PA * 2)
#define S_AH (S_BL + 256 * PA * 2)
#define S_AL (S_AH + 128 * PA * 2)
#define KV_SMEM_TOTAL (S_AL + 128 * PA * 2)

// ---------------- weight transposes + slot init ----------------
__global__ void sa_prep(const float* __restrict__ wq, const float* __restrict__ wih,
                        const float* __restrict__ whh, const float* __restrict__ w1,
                        const float* __restrict__ w2, const float* __restrict__ mu,
                        const float* __restrict__ ls, const float* __restrict__ noise) {
    int i = blockIdx.x * blockDim.x + threadIdx.x;
    if (i < DD * DD)  { int a = i / DD, j = i % DD; g_wqt[i] = wq[j * DD + a]; }
    if (i < DD * 384) { int d = i / 384, g = i % 384;
        g_wiht[i] = wih[g * DD + d]; g_whht[i] = whh[g * DD + d]; }
    if (i < DD * HH)  { int j = i / HH, m = i % HH; g_w1t[i] = w1[m * DD + j]; }
    if (i < HH * DD)  { int m = i / DD, j = i % DD; g_w2t[i] = w2[j * HH + m]; }
    if (i < SS * DD) {
        float v = mu[i] + expf(ls[i]) * noise[i];
        for (int b = 0; b < BB; ++b) g_slots[b * SS * DD + i] = v;
    }
}

// -------- LN(inputs) + K/V projection via mma.sync bf16-split (3 passes) -------
__global__ __launch_bounds__(256, 1)
void sa_kv(const float* __restrict__ inp, const float* __restrict__ nig,
           const float* __restrict__ nib, const float* __restrict__ bk,
           const float* __restrict__ bv, const float* __restrict__ wk,
           const float* __restrict__ wv) {
    extern __shared__ __align__(128) char smem[];
    const uint32_t sb = smem_u32(smem);
    const int tid = threadIdx.x;
    const int wid = tid >> 5;
    const int lane = tid & 31;

    for (int idx = tid; idx < 256 * DD; idx += 256) {
        int row = idx >> 7, k = idx & 127;
        float w = (row < 128) ? wk[row * DD + k] : wv[(row - 128) * DD + k];
        __nv_bfloat16 hi = __float2bfloat16(w);
        __nv_bfloat16 lo = __float2bfloat16(w - __bfloat162float(hi));
        uint32_t off = (uint32_t)(row * PA + k) * 2;
        *(__nv_bfloat16*)(smem + S_BH + off) = hi;
        *(__nv_bfloat16*)(smem + S_BL + off) = lo;
    }
    for (int c = tid; c < 256; c += 256)
        *(float*)(smem + S_BIAS + c * 4) = (c < DD) ? bk[c] : bv[c - DD];

    float4 lg4 = *(const float4*)(nig + lane * 4);
    float4 lb4 = *(const float4*)(nib + lane * 4);

    const int a_rr = lane & 7;
    const int a_g  = lane >> 3;
    const int a_ro = a_rr + ((a_g & 1) ? 8 : 0);
    const int a_ko = (a_g & 2) ? 8 : 0;
    const int b_rr = lane & 7;
    const int b_ko = (lane & 8) ? 8 : 0;
    const int r0 = wid * 16;

    const int ntiles = BB * NN / 128;   // 2048
    for (int tile = blockIdx.x; tile < ntiles; tile += gridDim.x) {
        size_t m0 = (size_t)tile * 128;
        #pragma unroll
        for (int rr = 0; rr < 16; ++rr) {
            int row = wid * 16 + rr;
            float4 xv = *(const float4*)(inp + (m0 + row) * DD + lane * 4);
            float s1 = xv.x + xv.y + xv.z + xv.w;
            float s2 = xv.x * xv.x + xv.y * xv.y + xv.z * xv.z + xv.w * xv.w;
            #pragma unroll
            for (int o = 16; o > 0; o >>= 1) {
                s1 += __shfl_xor_sync(0xffffffffu, s1, o);
                s2 += __shfl_xor_sync(0xffffffffu, s2, o);
            }
            float muv = s1 * (1.f / DD);
            float var = s2 * (1.f / DD) - muv * muv;
            float rs = rsqrtf(var + LN_EPS);
            float x0 = (xv.x - muv) * rs * lg4.x + lb4.x;
            float x1 = (xv.y - muv) * rs * lg4.y + lb4.y;
            float x2 = (xv.z - muv) * rs * lg4.z + lb4.z;
            float x3 = (xv.w - muv) * rs * lg4.w + lb4.w;
            __nv_bfloat16 h0 = __float2bfloat16(x0), h1 = __float2bfloat16(x1);
            __nv_bfloat16 h2 = __float2bfloat16(x2), h3 = __float2bfloat16(x3);
            __nv_bfloat16 l0 = __float2bfloat16(x0 - __bfloat162float(h0));
            __nv_bfloat16 l1 = __float2bfloat16(x1 - __bfloat162float(h1));
            __nv_bfloat16 l2 = __float2bfloat16(x2 - __bfloat162float(h2));
            __nv_bfloat16 l3 = __float2bfloat16(x3 - __bfloat162float(h3));
            uint2 hv, lv;
            hv.x = ((uint32_t)__bfloat16_as_ushort(h1) << 16) | __bfloat16_as_ushort(h0);
            hv.y = ((uint32_t)__bfloat16_as_ushort(h3) << 16) | __bfloat16_as_ushort(h2);
            lv.x = ((uint32_t)__bfloat16_as_ushort(l1) << 16) | __bfloat16_as_ushort(l0);
            lv.y = ((uint32_t)__bfloat16_as_ushort(l3) << 16) | __bfloat16_as_ushort(l2);
            uint32_t off = (uint32_t)(row * PA + lane * 4) * 2;
            *(uint2*)(smem + S_AH + off) = hv;
            *(uint2*)(smem + S_AL + off) = lv;
        }
        __syncthreads();
        float acc[32][4];
        #pragma unroll
        for (int nt = 0; nt < 32; ++nt) {
            acc[nt][0] = 0.f; acc[nt][1] = 0.f; acc[nt][2] = 0.f; acc[nt][3] = 0.f;
        }
        #pragma unroll 1
        for (int ks = 0; ks < 8; ++ks) {
            int k0 = ks * 16;
            uint32_t ah[4], al[4];
            uint32_t aoff = (uint32_t)((r0 + a_ro) * PA + k0 + a_ko) * 2;
            ldsm_x4(ah, sb + S_AH + aoff);
            ldsm_x4(al, sb + S_AL + aoff);
            uint32_t boff = (uint32_t)(b_rr * PA + k0 + b_ko) * 2;
            #pragma unroll
            for (int nt = 0; nt < 32; ++nt) {
                uint32_t bo = boff + (uint32_t)(nt * 8 * PA) * 2;
                uint32_t bh[2], bl[2];
                ldsm_x2(bh, sb + S_BH + bo);
                ldsm_x2(bl, sb + S_BL + bo);
                mma_bf16(acc[nt], ah, bh);
                mma_bf16(acc[nt], ah, bl);
                mma_bf16(acc[nt], al, bh);
            }
        }
        __syncthreads();
        {
            int rbase = (int)(m0 + r0 + (lane >> 2));
            int cq = (lane & 3) * 2;
            #pragma unroll
            for (int nt = 0; nt < 32; ++nt) {
                int col = nt * 8 + cq;
                float2 bias = *(float2*)(smem + S_BIAS + col * 4);
                float* base = (nt < 16) ? g_K : g_V;
                int c = (nt < 16) ? col : col - 128;
                *(float2*)(base + (size_t)rbase * DD + c)
                    = make_float2(acc[nt][0] + bias.x, acc[nt][1] + bias.y);
                *(float2*)(base + (size_t)(rbase + 8) * DD + c)
                    = make_float2(acc[nt][2] + bias.x, acc[nt][3] + bias.y);
            }
        }
    }
}

// ---------------- q = LN(slots; ns) @ wq^T + bq (initial q only) --------------
__global__ __launch_bounds__(128)
void sa_q(const float* __restrict__ nsg, const float* __restrict__ nsb,
          const float* __restrict__ bq) {
    __shared__ float xn[DD];
    __shared__ float rs1[4], rs2[4];
    int row = blockIdx.x;
    int tid = threadIdx.x;
    int lane = tid & 31, w = tid >> 5;
    float x = g_slots[row * DD + tid];
    float s1 = x, s2 = x * x;
    #pragma unroll
    for (int o = 16; o > 0; o >>= 1) {
        s1 += __shfl_xor_sync(0xffffffffu, s1, o);
        s2 += __shfl_xor_sync(0xffffffffu, s2, o);
    }
    if (lane == 0) { rs1[w] = s1; rs2[w] = s2; }
    __syncthreads();
    float sum = rs1[0] + rs1[1] + rs1[2] + rs1[3];
    float sq  = rs2[0] + rs2[1] + rs2[2] + rs2[3];
    float mu = sum * (1.f / DD);
    float var = sq * (1.f / DD) - mu * mu;
    float rstd = rsqrtf(var + LN_EPS);
    xn[tid] = (x - mu) * rstd * nsg[tid] + nsb[tid];
    __syncthreads();
    float acc = bq[tid];
    #pragma unroll 4
    for (int i = 0; i < DD; ++i) acc += xn[i] * g_wqt[i * DD + tid];
    g_q[row * DD + tid] = acc;
}

// ---------------- fused attention over one 64-token chunk ----------------
#define ATTN_SMEM ((CHUNK * PF + SS * DD + CHUNK * SS + 2 * SS * DD) * 4)
__global__ __launch_bounds__(256, 4)
void sa_attn() {
    extern __shared__ float sm[];
    float* Kst  = sm;                       // [t][PF]
    float* qs   = Kst + CHUNK * PF;         // [s][DD]
    float* att  = qs + SS * DD;             // [t][SS]
    float* updp = att + CHUNK * SS;         // [2][SS*DD]
    const int tid = threadIdx.x;
    const int b = blockIdx.y;
    const int n0 = blockIdx.x * CHUNK;
    {
        const float4* s4 = (const float4*)(g_q + b * SS * DD);
        float4* d4 = (float4*)qs;
        for (int i = tid; i < SS * DD / 4; i += 256) d4[i] = s4[i];
    }
    const float4* Kp4 = (const float4*)(g_K + ((size_t)b * NN + n0) * DD);
    for (int i4 = tid; i4 < CHUNK * 32; i4 += 256) {
        float4 kv = Kp4[i4];
        int tok = i4 >> 5;
        int c = i4 & 31;
        *(float4*)(Kst + tok * PF + c * 4) = kv;
    }
    __syncthreads();
    {
        const int t = tid & 63;
        const int s0 = (tid >> 6) * 2;
        float l0 = 0.f, l1 = 0.f;
        const float* kp = Kst + t * PF;
        const float* q0p = qs + s0 * DD;
        const float* q1p = qs + (s0 + 1) * DD;
        #pragma unroll 8
        for (int k = 0; k < DD; k += 4) {
            float4 kk = *(const float4*)(kp + k);
            float4 a0 = *(const float4*)(q0p + k);
            float4 a1 = *(const float4*)(q1p + k);
            l0 += kk.x * a0.x + kk.y * a0.y + kk.z * a0.z + kk.w * a0.w;
            l1 += kk.x * a1.x + kk.y * a1.y + kk.z * a1.z + kk.w * a1.w;
        }
        att[t * 8 + s0]     = l0 * QK_SCALE;
        att[t * 8 + s0 + 1] = l1 * QK_SCALE;
    }
    __syncthreads();
    if (tid < CHUNK) {
        float l[8];
        #pragma unroll
        for (int s = 0; s < 8; ++s) l[s] = att[tid * 8 + s];
        float mx = l[0];
        #pragma unroll
        for (int s = 1; s < 8; ++s) mx = fmaxf(mx, l[s]);
        float sum = 0.f;
        #pragma unroll
        for (int s = 0; s < 8; ++s) { l[s] = expf(l[s] - mx); sum += l[s]; }
        float inv = 1.f / sum;
        #pragma unroll
        for (int s = 0; s < 8; ++s) att[tid * 8 + s] = l[s] * inv;
    }
    __syncthreads();
    {
        int w = tid >> 5, lane = tid & 31;
        float v = att[lane * 8 + w] + att[(lane + 32) * 8 + w];
        #pragma unroll
        for (int o = 16; o > 0; o >>= 1) v += __shfl_xor_sync(0xffffffffu, v, o);
        if (lane == 0) g_normp[((size_t)blockIdx.x * BB + b) * SS + w] = v;
    }
    const float* Vp = g_V + ((size_t)b * NN + n0) * DD;
    {
        const int tq = tid >> 6;
        const int u = tid & 63;
        const int dp = u * 2;
        float ax[8], ay[8];
        #pragma unroll
        for (int s = 0; s < 8; ++s) { ax[s] = 0.f; ay[s] = 0.f; }
        #pragma unroll 4
        for (int tt = 0; tt < 16; ++tt) {
            int t = tq * 16 + tt;
            float2 vv = *(const float2*)(Vp + t * DD + dp);
            float4 w0 = *(const float4*)(att + t * 8);
            float4 w1 = *(const float4*)(att + t * 8 + 4);
            ax[0] += w0.x * vv.x; ay[0] += w0.x * vv.y;
            ax[1] += w0.y * vv.x; ay[1] += w0.y * vv.y;
            ax[2] += w0.z * vv.x; ay[2] += w0.z * vv.y;
            ax[3] += w0.w * vv.x; ay[3] += w0.w * vv.y;
            ax[4] += w1.x * vv.x; ay[4] += w1.x * vv.y;
            ax[5] += w1.y * vv.x; ay[5] += w1.y * vv.y;
            ax[6] += w1.z * vv.x; ay[6] += w1.z * vv.y;
            ax[7] += w1.w * vv.x; ay[7] += w1.w * vv.y;
        }
        float* buf = updp + (tq & 1) * (SS * DD);
        if (tq < 2) {
            #pragma unroll
            for (int s = 0; s < 8; ++s)
                *(float2*)(buf + s * DD + dp) = make_float2(ax[s], ay[s]);
        }
        __syncthreads();
        if (tq >= 2) {
            #pragma unroll
            for (int s = 0; s < 8; ++s) {
                float2 old = *(float2*)(buf + s * DD + dp);
                *(float2*)(buf + s * DD + dp)
                    = make_float2(old.x + ax[s], old.y + ay[s]);
            }
        }
    }
    __syncthreads();
    float* dst = g_updp + ((size_t)blockIdx.x * BB + b) * (SS * DD);
    for (int o = tid; o < SS * DD; o += 256)
        dst[o] = updp[o] + updp[o + SS * DD];
}

// ---- fused chunk-reduce + GRU + LN + MLP + residual + next-iter q -------------
// ONE block per batch (64 blocks x 512 threads): weights read once per block.
__global__ __launch_bounds__(512)
void sa_update(const float* __restrict__ bih, const float* __restrict__ bhh,
               const float* __restrict__ mg, const float* __restrict__ mb,
               const float* __restrict__ b1, const float* __restrict__ b2,
               const float* __restrict__ nsg, const float* __restrict__ nsb,
               const float* __restrict__ bq,
               float* __restrict__ outbuf, int write_out) {
    __shared__ float su[SS * DD], sh[SS * DD], sn[SS * DD], xn[SS * DD];
    __shared__ float h1s[SS * HH];
    __shared__ float nsum[SS];
    __shared__ float red[64];
    const int b = blockIdx.x;
    const int tid = threadIdx.x;
    const int lane = tid & 31, w = tid >> 5;       // 16 warps
    const int j = tid & 127;
    const int grp = tid >> 7;                      // 0..3
    const int s0 = grp * 2, s1g = s0 + 1;

    // norms: warp w covers slot w>>1, half (w&1)
    {
        int c = tid & 63, s = tid >> 6;
        float v = g_normp[((size_t)c * BB + b) * SS + s];
        #pragma unroll
        for (int o = 16; o > 0; o >>= 1) v += __shfl_xor_sync(0xffffffffu, v, o);
        if (lane == 0) red[w] = v;
    }
    __syncthreads();
    if (tid < SS) nsum[tid] = fmaxf(red[2 * tid] + red[2 * tid + 1], 1e-8f);
    __syncthreads();
    // chunk-reduce (coalesced 4KB rows) + slot load
    {
        float a0 = 0.f, a1 = 0.f;
        #pragma unroll 8
        for (int c = 0; c < NCHUNK; ++c) {
            const float* src = g_updp + ((size_t)c * BB + b) * (SS * DD);
            a0 += src[tid];
            a1 += src[tid + 512];
        }
        su[tid]       = a0 / nsum[tid >> 7];
        su[tid + 512] = a1 / nsum[(tid >> 7) + 4];
        sh[tid]       = g_slots[b * SS * DD + tid];
        sh[tid + 512] = g_slots[b * SS * DD + tid + 512];
    }
    __syncthreads();
    // GRU: thread handles column j for slots s0, s1g
    float sn0v, sn1v;
    {
        float ir0 = 0, iz0 = 0, in0 = 0, hr0 = 0, hz0 = 0, hn0 = 0;
        float ir1 = 0, iz1 = 0, in1 = 0, hr1 = 0, hz1 = 0, hn1 = 0;
        #pragma unroll 4
        for (int d = 0; d < DD; ++d) {
            float wr = g_wiht[d * 384 + j];
            float wz = g_wiht[d * 384 + 128 + j];
            float wn = g_wiht[d * 384 + 256 + j];
            float vr = g_whht[d * 384 + j];
            float vz = g_whht[d * 384 + 128 + j];
            float vn = g_whht[d * 384 + 256 + j];
            float u0 = su[s0 * DD + d], h0 = sh[s0 * DD + d];
            float u1 = su[s1g * DD + d], h1v = sh[s1g * DD + d];
            ir0 += wr * u0; iz0 += wz * u0; in0 += wn * u0;
            hr0 += vr * h0; hz0 += vz * h0; hn0 += vn * h0;
            ir1 += wr * u1; iz1 += wz * u1; in1 += wn * u1;
            hr1 += vr * h1v; hz1 += vz * h1v; hn1 += vn * h1v;
        }
        float bir = bih[j], biz = bih[j + 128], bin = bih[j + 256];
        float bhr = bhh[j], bhz = bhh[j + 128], bhn = bhh[j + 256];
        float r0 = 1.f / (1.f + expf(-(ir0 + bir + hr0 + bhr)));
        float z0 = 1.f / (1.f + expf(-(iz0 + biz + hz0 + bhz)));
        float n0 = tanhf(in0 + bin + r0 * (hn0 + bhn));
        sn0v = (1.f - z0) * n0 + z0 * sh[s0 * DD + j];
        float r1 = 1.f / (1.f + expf(-(ir1 + bir + hr1 + bhr)));
        float z1 = 1.f / (1.f + expf(-(iz1 + biz + hz1 + bhz)));
        float n1 = tanhf(in1 + bin + r1 * (hn1 + bhn));
        sn1v = (1.f - z1) * n1 + z1 * sh[s1g * DD + j];
        sn[s0 * DD + j] = sn0v;
        sn[s1g * DD + j] = sn1v;
    }
    // LN (mlp ln): group grp (4 warps) reduces its 2 slots
    {
        float s1a = sn0v, s2a = sn0v * sn0v, s1c = sn1v, s2c = sn1v * sn1v;
        #pragma unroll
        for (int o = 16; o > 0; o >>= 1) {
            s1a += __shfl_xor_sync(0xffffffffu, s1a, o);
            s2a += __shfl_xor_sync(0xffffffffu, s2a, o);
            s1c += __shfl_xor_sync(0xffffffffu, s1c, o);
            s2c += __shfl_xor_sync(0xffffffffu, s2c, o);
        }
        if (lane == 0) {
            red[w * 4 + 0] = s1a; red[w * 4 + 1] = s2a;
            red[w * 4 + 2] = s1c; red[w * 4 + 3] = s2c;
        }
        __syncthreads();
        int wb = grp * 4;
        float m0 = (red[wb*4+0] + red[(wb+1)*4+0] + red[(wb+2)*4+0] + red[(wb+3)*4+0]) * (1.f/DD);
        float e0 = (red[wb*4+1] + red[(wb+1)*4+1] + red[(wb+2)*4+1] + red[(wb+3)*4+1]) * (1.f/DD);
        float m1 = (red[wb*4+2] + red[(wb+1)*4+2] + red[(wb+2)*4+2] + red[(wb+3)*4+2]) * (1.f/DD);
        float e1 = (red[wb*4+3] + red[(wb+1)*4+3] + red[(wb+2)*4+3] + red[(wb+3)*4+3]) * (1.f/DD);
        float r0 = rsqrtf(e0 - m0 * m0 + LN_EPS);
        float r1 = rsqrtf(e1 - m1 * m1 + LN_EPS);
        float mgj = mg[j], mbj = mb[j];
        xn[s0 * DD + j]  = (sn0v - m0) * r0 * mgj + mbj;
        xn[s1g * DD + j] = (sn1v - m1) * r1 * mgj + mbj;
    }
    __syncthreads();
    // h1 = gelu(xn @ w1^T + b1): thread (m = tid&255, sg = tid>>8) -> 4 slots
    {
        const int m = tid & 255;
        const int sg = tid >> 8;
        float acc[4] = {0, 0, 0, 0};
        #pragma unroll 4
        for (int d = 0; d < DD; ++d) {
            float wv = g_w1t[d * HH + m];
            #pragma unroll
            for (int k = 0; k < 4; ++k) acc[k] += xn[(sg * 4 + k) * DD + d] * wv;
        }
        float bm = b1[m];
        #pragma unroll
        for (int k = 0; k < 4; ++k) {
            float g = acc[k] + bm;
            h1s[(sg * 4 + k) * HH + m] = 0.5f * g * (1.f + erff(g * 0.7071067811865475f));
        }
    }
    __syncthreads();
    // out = sn + h1 @ w2^T + b2 (thread: column j, slots s0, s1g)
    float v0, v1;
    {
        float o0 = 0, o1 = 0;
        #pragma unroll 4
        for (int m = 0; m < HH; ++m) {
            float wv = g_w2t[m * DD + j];
            o0 += h1s[s0 * HH + m] * wv;
            o1 += h1s[s1g * HH + m] * wv;
        }
        float b2j = b2[j];
        v0 = sn[s0 * DD + j] + o0 + b2j;
        v1 = sn[s1g * DD + j] + o1 + b2j;
        if (write_out) {
            outbuf[(b * SS + s0) * DD + j] = v0;
            outbuf[(b * SS + s1g) * DD + j] = v1;
        } else {
            g_slots[(b * SS + s0) * DD + j] = v0;
            g_slots[(b * SS + s1g) * DD + j] = v1;
        }
    }
    if (!write_out) {
        // q for next iter: LN(ns) of new slots + @ wq^T + bq
        __syncthreads();
        {
            float s1a = v0, s2a = v0 * v0, s1c = v1, s2c = v1 * v1;
            #pragma unroll
            for (int o = 16; o > 0; o >>= 1) {
                s1a += __shfl_xor_sync(0xffffffffu, s1a, o);
                s2a += __shfl_xor_sync(0xffffffffu, s2a, o);
                s1c += __shfl_xor_sync(0xffffffffu, s1c, o);
                s2c += __shfl_xor_sync(0xffffffffu, s2c, o);
            }
            if (lane == 0) {
                red[w * 4 + 0] = s1a; red[w * 4 + 1] = s2a;
                red[w * 4 + 2] = s1c; red[w * 4 + 3] = s2c;
            }
            __syncthreads();
            int wb = grp * 4;
            float m0 = (red[wb*4+0] + red[(wb+1)*4+0] + red[(wb+2)*4+0] + red[(wb+3)*4+0]) * (1.f/DD);
            float e0 = (red[wb*4+1] + red[(wb+1)*4+1] + red[(wb+2)*4+1] + red[(wb+3)*4+1]) * (1.f/DD);
            float m1 = (red[wb*4+2] + red[(wb+1)*4+2] + red[(wb+2)*4+2] + red[(wb+3)*4+2]) * (1.f/DD);
            float e1 = (red[wb*4+3] + red[(wb+1)*4+3] + red[(wb+2)*4+3] + red[(wb+3)*4+3]) * (1.f/DD);
            float r0 = rsqrtf(e0 - m0 * m0 + LN_EPS);
            float r1 = rsqrtf(e1 - m1 * m1 + LN_EPS);
            float ng = nsg[j], nb = nsb[j];
            xn[s0 * DD + j]  = (v0 - m0) * r0 * ng + nb;
            xn[s1g * DD + j] = (v1 - m1) * r1 * ng + nb;
        }
        __syncthreads();
        {
            float q0 = 0, q1 = 0;
            #pragma unroll 4
            for (int i = 0; i < DD; ++i) {
                float wv = g_wqt[i * DD + j];
                q0 += xn[s0 * DD + i] * wv;
                q1 += xn[s1g * DD + i] * wv;
            }
            float bqj = bq[j];
            g_q[(b * SS + s0) * DD + j] = q0 + bqj;
            g_q[(b * SS + s1g) * DD + j] = q1 + bqj;
        }
    }
}

// ---------------- launch ----------------
extern "C" void kernel_launch(void* const* d_in, const int* in_sizes, int n_in,
                              void* d_out, int out_size) {
    const float* inputs = (const float*)d_in[0];
    const float* noise  = (const float*)d_in[1];
    const float* mu     = (const float*)d_in[2];
    const float* lsig   = (const float*)d_in[3];
    const float* wq     = (const float*)d_in[4];
    const float* bq     = (const float*)d_in[5];
    const float* wk     = (const float*)d_in[6];
    const float* bk     = (const float*)d_in[7];
    const float* wv     = (const float*)d_in[8];
    const float* bv     = (const float*)d_in[9];
    const float* gwih   = (const float*)d_in[10];
    const float* gwhh   = (const float*)d_in[11];
    const float* gbih   = (const float*)d_in[12];
    const float* gbhh   = (const float*)d_in[13];
    const float* nsg    = (const float*)d_in[14];
    const float* nsb    = (const float*)d_in[15];
    const float* nig    = (const float*)d_in[16];
    const float* nib    = (const float*)d_in[17];
    const float* mlg    = (const float*)d_in[18];
    const float* mlb    = (const float*)d_in[19];
    const float* w1     = (const float*)d_in[20];
    const float* b1     = (const float*)d_in[21];
    const float* w2     = (const float*)d_in[22];
    const float* b2     = (const float*)d_in[23];
    float* out = (float*)d_out;

    cudaFuncSetAttribute(sa_kv,   cudaFuncAttributeMaxDynamicSharedMemorySize, KV_SMEM_TOTAL);
    cudaFuncSetAttribute(sa_attn, cudaFuncAttributeMaxDynamicSharedMemorySize, ATTN_SMEM);

    sa_prep<<<(DD * 384 + 255) / 256, 256>>>(wq, gwih, gwhh, w1, w2, mu, lsig, noise);
    sa_q<<<BB * SS, 128>>>(nsg, nsb, bq);          // initial q from initial slots
    sa_kv<<<148, 256, KV_SMEM_TOTAL>>>(inputs, nig, nib, bk, bv, wk, wv);
    for (int it = 0; it < N_ITERS; ++it) {
        dim3 agrid(NCHUNK, BB);
        sa_attn<<<agrid, 256, ATTN_SMEM>>>();
        sa_update<<<BB, 512>>>(gbih, gbhh, mlg, mlb, b1, b2, nsg, nsb, bq,
                               out, it == N_ITERS - 1 ? 1 : 0);
    }
}

// round 17
// speedup vs baseline: 1.0890x; 1.0890x over previous
#include <cuda_runtime.h>
#include <cuda_bf16.h>
#include <math.h>
#include <stdint.h>

#define BB 64
#define NN 4096
#define DD 128
#define SS 8
#define HH 256
#define N_ITERS 3
#define LN_EPS 1e-5f
#define QK_SCALE 0.08838834764831845f
#define CHUNK 64
#define NCHUNK (NN / CHUNK)
#define PF 132   // K chunk smem pitch in floats

// ---------------- device scratch ----------------
__device__ float g_K[BB * NN * DD];
__device__ float g_V[BB * NN * DD];
__device__ float g_slots[BB * SS * DD];
__device__ float g_q[BB * SS * DD];
__device__ float g_updp[NCHUNK * BB * SS * DD];
__device__ float g_normp[NCHUNK * BB * SS];
__device__ float g_wqt[DD * DD];
__device__ float g_wiht[DD * 3 * DD];
__device__ float g_whht[DD * 3 * DD];
__device__ float g_w1t[DD * HH];
__device__ float g_w2t[HH * DD];

__device__ __forceinline__ uint32_t smem_u32(const void* p) {
    uint32_t a;
    asm("{ .reg .u64 t; cvta.to.shared.u64 t, %1; cvt.u32.u64 %0, t; }"
        : "=r"(a) : "l"(p));
    return a;
}
__device__ __forceinline__ void ldsm_x4(uint32_t* r, uint32_t addr) {
    asm volatile("ldmatrix.sync.aligned.m8n8.x4.shared.b16 {%0,%1,%2,%3}, [%4];"
                 : "=r"(r[0]), "=r"(r[1]), "=r"(r[2]), "=r"(r[3]) : "r"(addr));
}
__device__ __forceinline__ void ldsm_x2(uint32_t* r, uint32_t addr) {
    asm volatile("ldmatrix.sync.aligned.m8n8.x2.shared.b16 {%0,%1}, [%2];"
                 : "=r"(r[0]), "=r"(r[1]) : "r"(addr));
}
__device__ __forceinline__ void mma_bf16(float* c, const uint32_t* a, const uint32_t* b) {
    asm volatile(
        "mma.sync.aligned.m16n8k16.row.col.f32.bf16.bf16.f32 "
        "{%0,%1,%2,%3}, {%4,%5,%6,%7}, {%8,%9}, {%0,%1,%2,%3};"
        : "+f"(c[0]), "+f"(c[1]), "+f"(c[2]), "+f"(c[3])
        : "r"(a[0]), "r"(a[1]), "r"(a[2]), "r"(a[3]), "r"(b[0]), "r"(b[1]));
}

// smem layout for sa_kv (bytes); pitch 136 bf16 (272B) de-conflicts ldmatrix
#define PA 136
#define S_BIAS 0
#define S_BH 1024
#define S_BL (S_BH + 256 * PA * 2)
#define S_AH (S_BL + 256 * PA * 2)
#define S_AL (S_AH + 128 * PA * 2)
#define KV_SMEM_TOTAL (S_AL + 128 * PA * 2)

// ---------------- weight transposes + slot init ----------------
__global__ void sa_prep(const float* __restrict__ wq, const float* __restrict__ wih,
                        const float* __restrict__ whh, const float* __restrict__ w1,
                        const float* __restrict__ w2, const float* __restrict__ mu,
                        const float* __restrict__ ls, const float* __restrict__ noise) {
    int i = blockIdx.x * blockDim.x + threadIdx.x;
    if (i < DD * DD)  { int a = i / DD, j = i % DD; g_wqt[i] = wq[j * DD + a]; }
    if (i < DD * 384) { int d = i / 384, g = i % 384;
        g_wiht[i] = wih[g * DD + d]; g_whht[i] = whh[g * DD + d]; }
    if (i < DD * HH)  { int j = i / HH, m = i % HH; g_w1t[i] = w1[m * DD + j]; }
    if (i < HH * DD)  { int m = i / DD, j = i % DD; g_w2t[i] = w2[j * HH + m]; }
    if (i < SS * DD) {
        float v = mu[i] + expf(ls[i]) * noise[i];
        for (int b = 0; b < BB; ++b) g_slots[b * SS * DD + i] = v;
    }
}

// -------- LN(inputs) + K/V projection via mma.sync bf16-split (3 passes) -------
__global__ __launch_bounds__(256, 1)
void sa_kv(const float* __restrict__ inp, const float* __restrict__ nig,
           const float* __restrict__ nib, const float* __restrict__ bk,
           const float* __restrict__ bv, const float* __restrict__ wk,
           const float* __restrict__ wv) {
    extern __shared__ __align__(128) char smem[];
    const uint32_t sb = smem_u32(smem);
    const int tid = threadIdx.x;
    const int wid = tid >> 5;
    const int lane = tid & 31;

    for (int idx = tid; idx < 256 * DD; idx += 256) {
        int row = idx >> 7, k = idx & 127;
        float w = (row < 128) ? wk[row * DD + k] : wv[(row - 128) * DD + k];
        __nv_bfloat16 hi = __float2bfloat16(w);
        __nv_bfloat16 lo = __float2bfloat16(w - __bfloat162float(hi));
        uint32_t off = (uint32_t)(row * PA + k) * 2;
        *(__nv_bfloat16*)(smem + S_BH + off) = hi;
        *(__nv_bfloat16*)(smem + S_BL + off) = lo;
    }
    for (int c = tid; c < 256; c += 256)
        *(float*)(smem + S_BIAS + c * 4) = (c < DD) ? bk[c] : bv[c - DD];

    float4 lg4 = *(const float4*)(nig + lane * 4);
    float4 lb4 = *(const float4*)(nib + lane * 4);

    const int a_rr = lane & 7;
    const int a_g  = lane >> 3;
    const int a_ro = a_rr + ((a_g & 1) ? 8 : 0);
    const int a_ko = (a_g & 2) ? 8 : 0;
    const int b_rr = lane & 7;
    const int b_ko = (lane & 8) ? 8 : 0;
    const int r0 = wid * 16;

    const int ntiles = BB * NN / 128;   // 2048
    for (int tile = blockIdx.x; tile < ntiles; tile += gridDim.x) {
        size_t m0 = (size_t)tile * 128;
        #pragma unroll
        for (int rr = 0; rr < 16; ++rr) {
            int row = wid * 16 + rr;
            float4 xv = *(const float4*)(inp + (m0 + row) * DD + lane * 4);
            float s1 = xv.x + xv.y + xv.z + xv.w;
            float s2 = xv.x * xv.x + xv.y * xv.y + xv.z * xv.z + xv.w * xv.w;
            #pragma unroll
            for (int o = 16; o > 0; o >>= 1) {
                s1 += __shfl_xor_sync(0xffffffffu, s1, o);
                s2 += __shfl_xor_sync(0xffffffffu, s2, o);
            }
            float muv = s1 * (1.f / DD);
            float var = s2 * (1.f / DD) - muv * muv;
            float rs = rsqrtf(var + LN_EPS);
            float x0 = (xv.x - muv) * rs * lg4.x + lb4.x;
            float x1 = (xv.y - muv) * rs * lg4.y + lb4.y;
            float x2 = (xv.z - muv) * rs * lg4.z + lb4.z;
            float x3 = (xv.w - muv) * rs * lg4.w + lb4.w;
            __nv_bfloat16 h0 = __float2bfloat16(x0), h1 = __float2bfloat16(x1);
            __nv_bfloat16 h2 = __float2bfloat16(x2), h3 = __float2bfloat16(x3);
            __nv_bfloat16 l0 = __float2bfloat16(x0 - __bfloat162float(h0));
            __nv_bfloat16 l1 = __float2bfloat16(x1 - __bfloat162float(h1));
            __nv_bfloat16 l2 = __float2bfloat16(x2 - __bfloat162float(h2));
            __nv_bfloat16 l3 = __float2bfloat16(x3 - __bfloat162float(h3));
            uint2 hv, lv;
            hv.x = ((uint32_t)__bfloat16_as_ushort(h1) << 16) | __bfloat16_as_ushort(h0);
            hv.y = ((uint32_t)__bfloat16_as_ushort(h3) << 16) | __bfloat16_as_ushort(h2);
            lv.x = ((uint32_t)__bfloat16_as_ushort(l1) << 16) | __bfloat16_as_ushort(l0);
            lv.y = ((uint32_t)__bfloat16_as_ushort(l3) << 16) | __bfloat16_as_ushort(l2);
            uint32_t off = (uint32_t)(row * PA + lane * 4) * 2;
            *(uint2*)(smem + S_AH + off) = hv;
            *(uint2*)(smem + S_AL + off) = lv;
        }
        __syncthreads();
        float acc[32][4];
        #pragma unroll
        for (int nt = 0; nt < 32; ++nt) {
            acc[nt][0] = 0.f; acc[nt][1] = 0.f; acc[nt][2] = 0.f; acc[nt][3] = 0.f;
        }
        #pragma unroll 1
        for (int ks = 0; ks < 8; ++ks) {
            int k0 = ks * 16;
            uint32_t ah[4], al[4];
            uint32_t aoff = (uint32_t)((r0 + a_ro) * PA + k0 + a_ko) * 2;
            ldsm_x4(ah, sb + S_AH + aoff);
            ldsm_x4(al, sb + S_AL + aoff);
            uint32_t boff = (uint32_t)(b_rr * PA + k0 + b_ko) * 2;
            #pragma unroll
            for (int nt = 0; nt < 32; ++nt) {
                uint32_t bo = boff + (uint32_t)(nt * 8 * PA) * 2;
                uint32_t bh[2], bl[2];
                ldsm_x2(bh, sb + S_BH + bo);
                ldsm_x2(bl, sb + S_BL + bo);
                mma_bf16(acc[nt], ah, bh);
                mma_bf16(acc[nt], ah, bl);
                mma_bf16(acc[nt], al, bh);
            }
        }
        __syncthreads();
        {
            int rbase = (int)(m0 + r0 + (lane >> 2));
            int cq = (lane & 3) * 2;
            #pragma unroll
            for (int nt = 0; nt < 32; ++nt) {
                int col = nt * 8 + cq;
                float2 bias = *(float2*)(smem + S_BIAS + col * 4);
                float* base = (nt < 16) ? g_K : g_V;
                int c = (nt < 16) ? col : col - 128;
                *(float2*)(base + (size_t)rbase * DD + c)
                    = make_float2(acc[nt][0] + bias.x, acc[nt][1] + bias.y);
                *(float2*)(base + (size_t)(rbase + 8) * DD + c)
                    = make_float2(acc[nt][2] + bias.x, acc[nt][3] + bias.y);
            }
        }
    }
}

// ---------------- q = LN(slots; ns) @ wq^T + bq (initial q only) --------------
__global__ __launch_bounds__(128)
void sa_q(const float* __restrict__ nsg, const float* __restrict__ nsb,
          const float* __restrict__ bq) {
    __shared__ float xn[DD];
    __shared__ float rs1[4], rs2[4];
    int row = blockIdx.x;
    int tid = threadIdx.x;
    int lane = tid & 31, w = tid >> 5;
    float x = g_slots[row * DD + tid];
    float s1 = x, s2 = x * x;
    #pragma unroll
    for (int o = 16; o > 0; o >>= 1) {
        s1 += __shfl_xor_sync(0xffffffffu, s1, o);
        s2 += __shfl_xor_sync(0xffffffffu, s2, o);
    }
    if (lane == 0) { rs1[w] = s1; rs2[w] = s2; }
    __syncthreads();
    float sum = rs1[0] + rs1[1] + rs1[2] + rs1[3];
    float sq  = rs2[0] + rs2[1] + rs2[2] + rs2[3];
    float mu = sum * (1.f / DD);
    float var = sq * (1.f / DD) - mu * mu;
    float rstd = rsqrtf(var + LN_EPS);
    xn[tid] = (x - mu) * rstd * nsg[tid] + nsb[tid];
    __syncthreads();
    float acc = bq[tid];
    #pragma unroll 4
    for (int i = 0; i < DD; ++i) acc += xn[i] * g_wqt[i * DD + tid];
    g_q[row * DD + tid] = acc;
}

// ---------------- fused attention over one 64-token chunk ----------------
#define ATTN_SMEM ((CHUNK * PF + SS * DD + CHUNK * SS + 2 * SS * DD) * 4)
__global__ __launch_bounds__(256, 4)
void sa_attn() {
    extern __shared__ float sm[];
    float* Kst  = sm;                       // [t][PF]
    float* qs   = Kst + CHUNK * PF;         // [s][DD]
    float* att  = qs + SS * DD;             // [t][SS]
    float* updp = att + CHUNK * SS;         // [2][SS*DD]
    const int tid = threadIdx.x;
    const int b = blockIdx.y;
    const int n0 = blockIdx.x * CHUNK;
    {
        const float4* s4 = (const float4*)(g_q + b * SS * DD);
        float4* d4 = (float4*)qs;
        for (int i = tid; i < SS * DD / 4; i += 256) d4[i] = s4[i];
    }
    const float4* Kp4 = (const float4*)(g_K + ((size_t)b * NN + n0) * DD);
    for (int i4 = tid; i4 < CHUNK * 32; i4 += 256) {
        float4 kv = Kp4[i4];
        int tok = i4 >> 5;
        int c = i4 & 31;
        *(float4*)(Kst + tok * PF + c * 4) = kv;
    }
    __syncthreads();
    {
        const int t = tid & 63;
        const int s0 = (tid >> 6) * 2;
        float l0 = 0.f, l1 = 0.f;
        const float* kp = Kst + t * PF;
        const float* q0p = qs + s0 * DD;
        const float* q1p = qs + (s0 + 1) * DD;
        #pragma unroll 8
        for (int k = 0; k < DD; k += 4) {
            float4 kk = *(const float4*)(kp + k);
            float4 a0 = *(const float4*)(q0p + k);
            float4 a1 = *(const float4*)(q1p + k);
            l0 += kk.x * a0.x + kk.y * a0.y + kk.z * a0.z + kk.w * a0.w;
            l1 += kk.x * a1.x + kk.y * a1.y + kk.z * a1.z + kk.w * a1.w;
        }
        att[t * 8 + s0]     = l0 * QK_SCALE;
        att[t * 8 + s0 + 1] = l1 * QK_SCALE;
    }
    __syncthreads();
    if (tid < CHUNK) {
        float l[8];
        #pragma unroll
        for (int s = 0; s < 8; ++s) l[s] = att[tid * 8 + s];
        float mx = l[0];
        #pragma unroll
        for (int s = 1; s < 8; ++s) mx = fmaxf(mx, l[s]);
        float sum = 0.f;
        #pragma unroll
        for (int s = 0; s < 8; ++s) { l[s] = expf(l[s] - mx); sum += l[s]; }
        float inv = 1.f / sum;
        #pragma unroll
        for (int s = 0; s < 8; ++s) att[tid * 8 + s] = l[s] * inv;
    }
    __syncthreads();
    {
        int w = tid >> 5, lane = tid & 31;
        float v = att[lane * 8 + w] + att[(lane + 32) * 8 + w];
        #pragma unroll
        for (int o = 16; o > 0; o >>= 1) v += __shfl_xor_sync(0xffffffffu, v, o);
        if (lane == 0) g_normp[((size_t)blockIdx.x * BB + b) * SS + w] = v;
    }
    const float* Vp = g_V + ((size_t)b * NN + n0) * DD;
    {
        const int tq = tid >> 6;
        const int u = tid & 63;
        const int dp = u * 2;
        float ax[8], ay[8];
        #pragma unroll
        for (int s = 0; s < 8; ++s) { ax[s] = 0.f; ay[s] = 0.f; }
        #pragma unroll 4
        for (int tt = 0; tt < 16; ++tt) {
            int t = tq * 16 + tt;
            float2 vv = *(const float2*)(Vp + t * DD + dp);
            float4 w0 = *(const float4*)(att + t * 8);
            float4 w1 = *(const float4*)(att + t * 8 + 4);
            ax[0] += w0.x * vv.x; ay[0] += w0.x * vv.y;
            ax[1] += w0.y * vv.x; ay[1] += w0.y * vv.y;
            ax[2] += w0.z * vv.x; ay[2] += w0.z * vv.y;
            ax[3] += w0.w * vv.x; ay[3] += w0.w * vv.y;
            ax[4] += w1.x * vv.x; ay[4] += w1.x * vv.y;
            ax[5] += w1.y * vv.x; ay[5] += w1.y * vv.y;
            ax[6] += w1.z * vv.x; ay[6] += w1.z * vv.y;
            ax[7] += w1.w * vv.x; ay[7] += w1.w * vv.y;
        }
        float* buf = updp + (tq & 1) * (SS * DD);
        if (tq < 2) {
            #pragma unroll
            for (int s = 0; s < 8; ++s)
                *(float2*)(buf + s * DD + dp) = make_float2(ax[s], ay[s]);
        }
        __syncthreads();
        if (tq >= 2) {
            #pragma unroll
            for (int s = 0; s < 8; ++s) {
                float2 old = *(float2*)(buf + s * DD + dp);
                *(float2*)(buf + s * DD + dp)
                    = make_float2(old.x + ax[s], old.y + ay[s]);
            }
        }
    }
    __syncthreads();
    float* dst = g_updp + ((size_t)blockIdx.x * BB + b) * (SS * DD);
    for (int o = tid; o < SS * DD; o += 256)
        dst[o] = updp[o] + updp[o + SS * DD];
}

// -- fused chunk-reduce + GRU + LN + MLP + residual + next-iter q --------------
// ONE block per (b, slot): 512 blocks x 128 threads (R15 shape + q fusion).
__global__ __launch_bounds__(128)
void sa_update(const float* __restrict__ bih, const float* __restrict__ bhh,
               const float* __restrict__ mg, const float* __restrict__ mb,
               const float* __restrict__ b1, const float* __restrict__ b2,
               const float* __restrict__ nsg, const float* __restrict__ nsb,
               const float* __restrict__ bq,
               float* __restrict__ outbuf, int write_out) {
    __shared__ float su[DD], sh[DD], sn[DD], xn[DD];
    __shared__ float h1s[HH];
    __shared__ float red[8];
    const int b = blockIdx.x >> 3;
    const int s = blockIdx.x & 7;
    const int j = threadIdx.x;
    const int lane = j & 31, w = j >> 5;
    if (w == 0) {
        float ns = g_normp[((size_t)lane * BB + b) * SS + s]
                 + g_normp[((size_t)(lane + 32) * BB + b) * SS + s];
        #pragma unroll
        for (int o = 16; o > 0; o >>= 1) ns += __shfl_xor_sync(0xffffffffu, ns, o);
        if (lane == 0) red[0] = fmaxf(ns, 1e-8f);
    }
    {
        float a0 = 0.f;
        const size_t o0 = (size_t)s * DD + j;
        #pragma unroll 8
        for (int c = 0; c < NCHUNK; ++c)
            a0 += g_updp[((size_t)c * BB + b) * (SS * DD) + o0];
        sh[j] = g_slots[(b * SS + s) * DD + j];
        __syncthreads();
        su[j] = a0 / red[0];
    }
    __syncthreads();
    float ir = 0, iz = 0, inn = 0, hr = 0, hz = 0, hn = 0;
    #pragma unroll 4
    for (int d = 0; d < DD; ++d) {
        float u = su[d], h = sh[d];
        ir  += g_wiht[d * 384 + j] * u;
        iz  += g_wiht[d * 384 + 128 + j] * u;
        inn += g_wiht[d * 384 + 256 + j] * u;
        hr  += g_whht[d * 384 + j] * h;
        hz  += g_whht[d * 384 + 128 + j] * h;
        hn  += g_whht[d * 384 + 256 + j] * h;
    }
    {
        float r = 1.f / (1.f + expf(-(ir + bih[j] + hr + bhh[j])));
        float z = 1.f / (1.f + expf(-(iz + bih[j + 128] + hz + bhh[j + 128])));
        float n = tanhf(inn + bih[j + 256] + r * (hn + bhh[j + 256]));
        sn[j] = (1.f - z) * n + z * sh[j];
    }
    __syncthreads();
    {
        float a = sn[j];
        float s1 = a, s2 = a * a;
        #pragma unroll
        for (int o = 16; o > 0; o >>= 1) {
            s1 += __shfl_xor_sync(0xffffffffu, s1, o);
            s2 += __shfl_xor_sync(0xffffffffu, s2, o);
        }
        if (lane == 0) { red[w] = s1; red[w + 4] = s2; }
        __syncthreads();
        float m = (red[0] + red[1] + red[2] + red[3]) * (1.f / DD);
        float v = (red[4] + red[5] + red[6] + red[7]) * (1.f / DD) - m * m;
        float rs = rsqrtf(v + LN_EPS);
        xn[j] = (a - m) * rs * mg[j] + mb[j];
    }
    __syncthreads();
    {
        float a0 = 0, a1 = 0;
        #pragma unroll 4
        for (int d = 0; d < DD; ++d) {
            float x = xn[d];
            a0 += x * g_w1t[d * HH + j];
            a1 += x * g_w1t[d * HH + j + 128];
        }
        float g0 = a0 + b1[j], g1 = a1 + b1[j + 128];
        h1s[j]       = 0.5f * g0 * (1.f + erff(g0 * 0.7071067811865475f));
        h1s[j + 128] = 0.5f * g1 * (1.f + erff(g1 * 0.7071067811865475f));
    }
    __syncthreads();
    float val;
    {
        float o = 0;
        #pragma unroll 4
        for (int m = 0; m < HH; ++m) o += h1s[m] * g_w2t[m * DD + j];
        val = sn[j] + o + b2[j];
        if (write_out) outbuf[(b * SS + s) * DD + j] = val;
        else           g_slots[(b * SS + s) * DD + j] = val;
    }
    if (!write_out) {
        // fused next-iter q: LN(ns) on new slot + wq^T column dot
        __syncthreads();
        {
            float s1 = val, s2 = val * val;
            #pragma unroll
            for (int o = 16; o > 0; o >>= 1) {
                s1 += __shfl_xor_sync(0xffffffffu, s1, o);
                s2 += __shfl_xor_sync(0xffffffffu, s2, o);
            }
            if (lane == 0) { red[w] = s1; red[w + 4] = s2; }
            __syncthreads();
            float m = (red[0] + red[1] + red[2] + red[3]) * (1.f / DD);
            float v = (red[4] + red[5] + red[6] + red[7]) * (1.f / DD) - m * m;
            float rs = rsqrtf(v + LN_EPS);
            xn[j] = (val - m) * rs * nsg[j] + nsb[j];
        }
        __syncthreads();
        {
            float acc = bq[j];
            #pragma unroll 4
            for (int i = 0; i < DD; ++i) acc += xn[i] * g_wqt[i * DD + j];
            g_q[(b * SS + s) * DD + j] = acc;
        }
    }
}

// ---------------- launch ----------------
extern "C" void kernel_launch(void* const* d_in, const int* in_sizes, int n_in,
                              void* d_out, int out_size) {
    const float* inputs = (const float*)d_in[0];
    const float* noise  = (const float*)d_in[1];
    const float* mu     = (const float*)d_in[2];
    const float* lsig   = (const float*)d_in[3];
    const float* wq     = (const float*)d_in[4];
    const float* bq     = (const float*)d_in[5];
    const float* wk     = (const float*)d_in[6];
    const float* bk     = (const float*)d_in[7];
    const float* wv     = (const float*)d_in[8];
    const float* bv     = (const float*)d_in[9];
    const float* gwih   = (const float*)d_in[10];
    const float* gwhh   = (const float*)d_in[11];
    const float* gbih   = (const float*)d_in[12];
    const float* gbhh   = (const float*)d_in[13];
    const float* nsg    = (const float*)d_in[14];
    const float* nsb    = (const float*)d_in[15];
    const float* nig    = (const float*)d_in[16];
    const float* nib    = (const float*)d_in[17];
    const float* mlg    = (const float*)d_in[18];
    const float* mlb    = (const float*)d_in[19];
    const float* w1     = (const float*)d_in[20];
    const float* b1     = (const float*)d_in[21];
    const float* w2     = (const float*)d_in[22];
    const float* b2     = (const float*)d_in[23];
    float* out = (float*)d_out;

    cudaFuncSetAttribute(sa_kv,   cudaFuncAttributeMaxDynamicSharedMemorySize, KV_SMEM_TOTAL);
    cudaFuncSetAttribute(sa_attn, cudaFuncAttributeMaxDynamicSharedMemorySize, ATTN_SMEM);

    sa_prep<<<(DD * 384 + 255) / 256, 256>>>(wq, gwih, gwhh, w1, w2, mu, lsig, noise);
    sa_q<<<BB * SS, 128>>>(nsg, nsb, bq);          // initial q from initial slots
    sa_kv<<<148, 256, KV_SMEM_TOTAL>>>(inputs, nig, nib, bk, bv, wk, wv);
    for (int it = 0; it < N_ITERS; ++it) {
        dim3 agrid(NCHUNK, BB);
        sa_attn<<<agrid, 256, ATTN_SMEM>>>();
        sa_update<<<BB * SS, 128>>>(gbih, gbhh, mlg, mlb, b1, b2, nsg, nsb, bq,
                                    out, it == N_ITERS - 1 ? 1 : 0);
    }
}